// round 13
// baseline (speedup 1.0000x reference)
#include <cuda_runtime.h>
#include <cuda_fp16.h>
#include <math.h>
#include <stdint.h>

#define H  1024
#define B  64
#define L  1024
#define VP 32000
#define VC 32000

// ---- flash attention config ----
#define CS   8
#define LPW  (L / CS / 8)
#define NPART 64

// ---- tf32 GEMM config (gru/concat) ----
#define TVL   128
#define KCL   32
#define PITCH 36
#define SM_GEMM3 ((2 * 2 * TVL * PITCH + 2 * 2 * B * PITCH) * 4)

// ---- logits fp16 GEMM ----
#define HPITCH 40      // halves per row in smem (80B: conflict-free ldmatrix)

#define GRU_ROWS   6144
#define GRU_SPLITS 2
#define CAT_ROWS   1024
#define CAT_SPLITS 4

// ---- scratch ----
__device__ __align__(16) float g_xh[2 * B * H];
__device__ __align__(16) float g_gatep[GRU_SPLITS * GRU_ROWS * B];
__device__ __align__(16) float g_hnew[B * H];
__device__ __align__(16) float g_hc[B * 2 * H];
__device__ __align__(16) float g_scores[B * L];
__device__ __align__(16) float g_ctxpart[B * NPART * H];
__device__ float g_pm[B * NPART];
__device__ float g_ps[B * NPART];
__device__ __align__(16) float g_cpart[CAT_SPLITS * CAT_ROWS * B];
__device__ __align__(16) __half g_concat_h[B * H];   // fp16 X for logits

__device__ __forceinline__ float warp_sum(float v) {
#pragma unroll
    for (int o = 16; o; o >>= 1) v += __shfl_xor_sync(0xffffffffu, v, o);
    return v;
}
__device__ __forceinline__ float f2tf32f(float x) {
    uint32_t u; asm("cvt.rna.tf32.f32 %0, %1;" : "=r"(u) : "f"(x));
    return __uint_as_float(u);
}
__device__ __forceinline__ void mma_tf32(float* c, const uint32_t* a,
                                         uint32_t b0, uint32_t b1) {
    asm volatile(
        "mma.sync.aligned.m16n8k8.row.col.f32.tf32.tf32.f32 "
        "{%0,%1,%2,%3}, {%4,%5,%6,%7}, {%8,%9}, {%0,%1,%2,%3};"
        : "+f"(c[0]), "+f"(c[1]), "+f"(c[2]), "+f"(c[3])
        : "r"(a[0]), "r"(a[1]), "r"(a[2]), "r"(a[3]), "r"(b0), "r"(b1));
}
__device__ __forceinline__ void mma_f16(float* c, const uint32_t* a,
                                        uint32_t b0, uint32_t b1) {
    asm volatile(
        "mma.sync.aligned.m16n8k16.row.col.f32.f16.f16.f32 "
        "{%0,%1,%2,%3}, {%4,%5,%6,%7}, {%8,%9}, {%0,%1,%2,%3};"
        : "+f"(c[0]), "+f"(c[1]), "+f"(c[2]), "+f"(c[3])
        : "r"(a[0]), "r"(a[1]), "r"(a[2]), "r"(a[3]), "r"(b0), "r"(b1));
}
// pack two fp32 into f16x2: lo in low half
__device__ __forceinline__ uint32_t h2pack(float lo, float hi) {
    uint32_t r; asm("cvt.rn.f16x2.f32 %0, %1, %2;" : "=r"(r) : "f"(hi), "f"(lo));
    return r;
}
__device__ __forceinline__ void ldsm_x4(uint32_t* r, uint32_t addr) {
    asm volatile("ldmatrix.sync.aligned.m8n8.x4.shared.b16 {%0,%1,%2,%3}, [%4];"
        : "=r"(r[0]), "=r"(r[1]), "=r"(r[2]), "=r"(r[3]) : "r"(addr));
}
__device__ __forceinline__ void ldsm_x2(uint32_t* r, uint32_t addr) {
    asm volatile("ldmatrix.sync.aligned.m8n8.x2.shared.b16 {%0,%1}, [%2];"
        : "=r"(r[0]), "=r"(r[1]) : "r"(addr));
}

// ---------------------------------------------------------------------------
// 0) pack x and h_prev
// ---------------------------------------------------------------------------
__global__ void pack_xh_kernel(const int* __restrict__ seq,
                               const float* __restrict__ hprev,
                               const float* __restrict__ emb) {
    int b = blockIdx.x, tid = threadIdx.x;
    ((float4*)(g_xh + (size_t)b * H))[tid] =
        ((const float4*)(emb + (size_t)seq[b] * H))[tid];
    ((float4*)(g_xh + (size_t)(B + b) * H))[tid] =
        ((const float4*)(hprev + (size_t)b * H))[tid];
}

// ---------------------------------------------------------------------------
// Generic SPLIT-3 tf32 GEMM (R10, measured-good accuracy)
// ---------------------------------------------------------------------------
__global__ __launch_bounds__(256) void gemm_part(
        const float* __restrict__ A0, const float* __restrict__ A1,
        const float* __restrict__ X0, const float* __restrict__ X1,
        float* __restrict__ outp, int ldA, int kPerSplit, int halfBlocks,
        int totalRows) {
    extern __shared__ float smf[];
    float* Wt = smf;
    float* Xt = smf + 2 * 2 * TVL * PITCH;

    int tid = threadIdx.x;
    int wid = tid >> 5, lane = tid & 31;
    int grp = lane >> 2, tig = lane & 3;
    int warpM = wid & 3, warpN = wid >> 2;

    const float* A = A0; const float* X = X0;
    int blk = blockIdx.x;
    int outRowBase = blk * TVL;
    if (halfBlocks > 0 && blk >= halfBlocks) { A = A1; X = X1; blk -= halfBlocks; }
    int a0 = blk * TVL;
    int kOff = blockIdx.y * kPerSplit;
    int nt = kPerSplit / KCL;

#define WP_(buf, part) (Wt + ((buf) * 2 + (part)) * TVL * PITCH)
#define XP_(buf, part) (Xt + ((buf) * 2 + (part)) * B * PITCH)

    float acc[2][4][4];
#pragma unroll
    for (int i = 0; i < 2; i++)
#pragma unroll
        for (int j = 0; j < 4; j++)
#pragma unroll
            for (int q = 0; q < 4; q++) acc[i][j][q] = 0.f;

#pragma unroll
    for (int r = 0; r < 4; r++) {
        int f = tid + r * 256;
        int v = f >> 3, kq = f & 7;
        float4 w4 = *(const float4*)(A + (size_t)(a0 + v) * ldA + kOff + kq * 4);
        float hx = f2tf32f(w4.x), hy = f2tf32f(w4.y), hz = f2tf32f(w4.z), hw = f2tf32f(w4.w);
        *(float4*)&WP_(0, 0)[v * PITCH + kq * 4] = make_float4(hx, hy, hz, hw);
        *(float4*)&WP_(0, 1)[v * PITCH + kq * 4] =
            make_float4(f2tf32f(w4.x - hx), f2tf32f(w4.y - hy),
                        f2tf32f(w4.z - hz), f2tf32f(w4.w - hw));
    }
#pragma unroll
    for (int r = 0; r < 2; r++) {
        int f = tid + r * 256;
        int xb = f >> 3, kq = f & 7;
        float4 x4 = *(const float4*)(X + (size_t)xb * ldA + kOff + kq * 4);
        float hx = f2tf32f(x4.x), hy = f2tf32f(x4.y), hz = f2tf32f(x4.z), hw = f2tf32f(x4.w);
        *(float4*)&XP_(0, 0)[xb * PITCH + kq * 4] = make_float4(hx, hy, hz, hw);
        *(float4*)&XP_(0, 1)[xb * PITCH + kq * 4] =
            make_float4(f2tf32f(x4.x - hx), f2tf32f(x4.y - hy),
                        f2tf32f(x4.z - hz), f2tf32f(x4.w - hw));
    }
    __syncthreads();

    for (int t = 0; t < nt; t++) {
        int cur = t & 1;
        float* WH = WP_(cur, 0); float* WL = WP_(cur, 1);
        float* XH = XP_(cur, 0); float* XL = XP_(cur, 1);
        float4 wpre[4], xpre[2];
        if (t + 1 < nt) {
            int kc = kOff + (t + 1) * KCL;
#pragma unroll
            for (int r = 0; r < 4; r++) {
                int f = tid + r * 256;
                int v = f >> 3, kq = f & 7;
                wpre[r] = *(const float4*)(A + (size_t)(a0 + v) * ldA + kc + kq * 4);
            }
#pragma unroll
            for (int r = 0; r < 2; r++) {
                int f = tid + r * 256;
                int xb = f >> 3, kq = f & 7;
                xpre[r] = *(const float4*)(X + (size_t)xb * ldA + kc + kq * 4);
            }
        }
#pragma unroll
        for (int ks = 0; ks < KCL / 8; ks++) {
            int k0 = ks * 8 + tig;
            uint32_t aH[2][4], aL[2][4];
#pragma unroll
            for (int mf = 0; mf < 2; mf++) {
                int mm = warpM * 32 + mf * 16 + grp;
                aH[mf][0] = __float_as_uint(WH[mm * PITCH + k0]);
                aH[mf][1] = __float_as_uint(WH[(mm + 8) * PITCH + k0]);
                aH[mf][2] = __float_as_uint(WH[mm * PITCH + k0 + 4]);
                aH[mf][3] = __float_as_uint(WH[(mm + 8) * PITCH + k0 + 4]);
                aL[mf][0] = __float_as_uint(WL[mm * PITCH + k0]);
                aL[mf][1] = __float_as_uint(WL[(mm + 8) * PITCH + k0]);
                aL[mf][2] = __float_as_uint(WL[mm * PITCH + k0 + 4]);
                aL[mf][3] = __float_as_uint(WL[(mm + 8) * PITCH + k0 + 4]);
            }
#pragma unroll
            for (int nf = 0; nf < 4; nf++) {
                int n = warpN * 32 + nf * 8 + grp;
                uint32_t bH0 = __float_as_uint(XH[n * PITCH + k0]);
                uint32_t bH1 = __float_as_uint(XH[n * PITCH + k0 + 4]);
                uint32_t bL0 = __float_as_uint(XL[n * PITCH + k0]);
                uint32_t bL1 = __float_as_uint(XL[n * PITCH + k0 + 4]);
#pragma unroll
                for (int mf = 0; mf < 2; mf++) {
                    mma_tf32(acc[mf][nf], aH[mf], bH0, bH1);
                    mma_tf32(acc[mf][nf], aH[mf], bL0, bL1);
                    mma_tf32(acc[mf][nf], aL[mf], bH0, bH1);
                }
            }
        }
        if (t + 1 < nt) {
            int nxt = cur ^ 1;
#pragma unroll
            for (int r = 0; r < 4; r++) {
                int f = tid + r * 256;
                int v = f >> 3, kq = f & 7;
                float hx = f2tf32f(wpre[r].x), hy = f2tf32f(wpre[r].y);
                float hz = f2tf32f(wpre[r].z), hw = f2tf32f(wpre[r].w);
                *(float4*)&WP_(nxt, 0)[v * PITCH + kq * 4] = make_float4(hx, hy, hz, hw);
                *(float4*)&WP_(nxt, 1)[v * PITCH + kq * 4] =
                    make_float4(f2tf32f(wpre[r].x - hx), f2tf32f(wpre[r].y - hy),
                                f2tf32f(wpre[r].z - hz), f2tf32f(wpre[r].w - hw));
            }
#pragma unroll
            for (int r = 0; r < 2; r++) {
                int f = tid + r * 256;
                int xb = f >> 3, kq = f & 7;
                float hx = f2tf32f(xpre[r].x), hy = f2tf32f(xpre[r].y);
                float hz = f2tf32f(xpre[r].z), hw = f2tf32f(xpre[r].w);
                *(float4*)&XP_(nxt, 0)[xb * PITCH + kq * 4] = make_float4(hx, hy, hz, hw);
                *(float4*)&XP_(nxt, 1)[xb * PITCH + kq * 4] =
                    make_float4(f2tf32f(xpre[r].x - hx), f2tf32f(xpre[r].y - hy),
                                f2tf32f(xpre[r].z - hz), f2tf32f(xpre[r].w - hw));
            }
        }
        __syncthreads();
    }
#undef WP_
#undef XP_

    float* o = outp + (size_t)blockIdx.y * totalRows * B;
#pragma unroll
    for (int mf = 0; mf < 2; mf++) {
        int vr = outRowBase + warpM * 32 + mf * 16 + grp;
#pragma unroll
        for (int nf = 0; nf < 4; nf++) {
            int bcol = warpN * 32 + nf * 8 + 2 * tig;
            o[(size_t)vr * B + bcol]           = acc[mf][nf][0];
            o[(size_t)vr * B + bcol + 1]       = acc[mf][nf][1];
            o[(size_t)(vr + 8) * B + bcol]     = acc[mf][nf][2];
            o[(size_t)(vr + 8) * B + bcol + 1] = acc[mf][nf][3];
        }
    }
}

// ---------------------------------------------------------------------------
// gate combine -> h_new
// ---------------------------------------------------------------------------
__global__ void gru_gate_kernel(const float* __restrict__ hprev,
                                const float* __restrict__ b_ih,
                                const float* __restrict__ b_hh,
                                float* __restrict__ hidden_out) {
    int tid = threadIdx.x;
    int b = tid & 63;
    int i = blockIdx.x * 4 + (tid >> 6);
#define GP(row) (g_gatep[(size_t)(row) * B + b] + \
                 g_gatep[(size_t)(GRU_ROWS + (row)) * B + b])
    float gir = GP(i),          giz = GP(H + i),      gin = GP(2 * H + i);
    float ghr = GP(3 * H + i),  ghz = GP(4 * H + i),  ghn = GP(5 * H + i);
#undef GP
    float r = 1.f / (1.f + expf(-(gir + b_ih[i] + ghr + b_hh[i])));
    float z = 1.f / (1.f + expf(-(giz + b_ih[H + i] + ghz + b_hh[H + i])));
    float n = tanhf(gin + b_ih[2 * H + i] + r * (ghn + b_hh[2 * H + i]));
    float hv = hprev[(size_t)b * H + i];
    float hn = (1.f - z) * n + z * hv;
    g_hnew[(size_t)b * H + i] = hn;
    g_hc[(size_t)b * 2 * H + i] = hn;
    hidden_out[(size_t)b * H + i] = hn;
}

// ---------------------------------------------------------------------------
// flash attention (measured 46.5us @ 77% DRAM)
// ---------------------------------------------------------------------------
__global__ __launch_bounds__(256) void flash2_kernel(const float* __restrict__ enc) {
    int b = blockIdx.x, ch = blockIdx.y;
    int w = threadIdx.x >> 5, lane = threadIdx.x & 31;
    int l0 = ch * (L / CS) + w * LPW;

    const float4* hb = (const float4*)(g_hnew + (size_t)b * H);
    float4 h[8];
#pragma unroll
    for (int q = 0; q < 8; q++) h[q] = hb[lane + q * 32];

    float4 acc[8];
#pragma unroll
    for (int q = 0; q < 8; q++) acc[q] = make_float4(0.f, 0.f, 0.f, 0.f);
    float m = -1e30f, ssum = 0.f;

    for (int j = 0; j < LPW; j++) {
        int l = l0 + j;
        const float4* er = (const float4*)(enc + ((size_t)l * B + b) * H);
        float4 e[8];
        float d = 0.f;
#pragma unroll
        for (int q = 0; q < 8; q++) {
            e[q] = er[lane + q * 32];
            d += e[q].x * h[q].x + e[q].y * h[q].y + e[q].z * h[q].z + e[q].w * h[q].w;
        }
        d = warp_sum(d);
        if (lane == 0) g_scores[b * L + l] = d;
        float nm = fmaxf(m, d);
        float sc = expf(m - nm);
        float p = expf(d - nm);
        ssum = ssum * sc + p;
#pragma unroll
        for (int q = 0; q < 8; q++) {
            acc[q].x = acc[q].x * sc + p * e[q].x;
            acc[q].y = acc[q].y * sc + p * e[q].y;
            acc[q].z = acc[q].z * sc + p * e[q].z;
            acc[q].w = acc[q].w * sc + p * e[q].w;
        }
        m = nm;
    }

    int pidx = b * NPART + ch * 8 + w;
    float4* pp = (float4*)(g_ctxpart + (size_t)pidx * H);
#pragma unroll
    for (int q = 0; q < 8; q++) pp[lane + q * 32] = acc[q];
    if (lane == 0) { g_pm[pidx] = m; g_ps[pidx] = ssum; }
}

__global__ void ctx_combine2_kernel() {
    int b = blockIdx.x, tid = threadIdx.x;
    __shared__ float sm[NPART], sw[NPART];
    if (tid < NPART) sm[tid] = g_pm[b * NPART + tid];
    __syncthreads();
    float gm = -1e30f;
#pragma unroll 8
    for (int c = 0; c < NPART; c++) gm = fmaxf(gm, sm[c]);
    if (tid < NPART) sw[tid] = expf(sm[tid] - gm);
    __syncthreads();
    float S = 0.f;
#pragma unroll 8
    for (int c = 0; c < NPART; c++) S += g_ps[b * NPART + c] * sw[c];
    float inv = 1.f / S;
    float4 a = make_float4(0.f, 0.f, 0.f, 0.f);
    for (int c = 0; c < NPART; c++) {
        float wgt = sw[c];
        float4 p = ((const float4*)(g_ctxpart + ((size_t)(b * NPART + c)) * H))[tid];
        a.x += wgt * p.x; a.y += wgt * p.y; a.z += wgt * p.z; a.w += wgt * p.w;
    }
    a.x *= inv; a.y *= inv; a.z *= inv; a.w *= inv;
    ((float4*)(g_hc + (size_t)b * 2 * H + H))[tid] = a;
}

// ---------------------------------------------------------------------------
// concat reduce + tanh -> g_concat_h (fp16)
// ---------------------------------------------------------------------------
__global__ void cat_reduce_kernel(const float* __restrict__ cb) {
    int tid = threadIdx.x;
    int b = tid & 63;
    int i = blockIdx.x * 4 + (tid >> 6);
    float s = 0.f;
#pragma unroll
    for (int y = 0; y < CAT_SPLITS; y++)
        s += g_cpart[(size_t)(y * CAT_ROWS + i) * B + b];
    g_concat_h[(size_t)b * H + i] = __float2half_rn(tanhf(s + cb[i]));
}

// ---------------------------------------------------------------------------
// logits: fp16 m16n8k16 GEMM with fp16-in-smem + ldmatrix fragments.
// Loader: LDG fp32 W -> cvt f16x2 -> STS (register-prefetch double buffer).
// Fragments: 1 ldmatrix.x4 per A-frag, 1 ldmatrix.x2 per B-frag.
// ---------------------------------------------------------------------------
__global__ __launch_bounds__(256) void logits_f16(
        const float* __restrict__ wp, const float* __restrict__ bp,
        const float* __restrict__ wc, const float* __restrict__ bc,
        float* __restrict__ out) {
    __shared__ __half Wt[2][TVL * HPITCH];   // 10240 halves/stage
    __shared__ __half Xt[2][B * HPITCH];     // 2560 halves/stage

    int tid = threadIdx.x;
    int wid = tid >> 5, lane = tid & 31;
    int grp = lane >> 2, tig = lane & 3;
    int warpM = wid & 3, warpN = wid >> 2;

    int v0 = blockIdx.x * TVL;
    const float* W; const float* bias; float* obase;
    if (v0 < VP) { W = wp; bias = bp; obase = out; }
    else { W = wc; bias = bc; obase = out + (size_t)B * VP; v0 -= VP; }

    float acc[2][4][4];
#pragma unroll
    for (int i = 0; i < 2; i++)
#pragma unroll
        for (int j = 0; j < 4; j++)
#pragma unroll
            for (int q = 0; q < 4; q++) acc[i][j][q] = 0.f;

    const int NT = H / KCL;   // 32

    // loader indices: W thread -> row wv = tid>>1, half-chunk wq = tid&1 (16 floats)
    //                 X thread -> row xb = tid>>2, chunk xq = tid&3 (8 halves)
    int wv = tid >> 1, wq = tid & 1;
    int xb = tid >> 2, xq = tid & 3;

    // ---- prime buffer 0 directly ----
    {
        const float* src = W + (size_t)(v0 + wv) * H + wq * 16;
        uint32_t hbuf[8];
#pragma unroll
        for (int r = 0; r < 4; r++) {
            float4 w4 = *(const float4*)(src + r * 4);
            hbuf[r * 2]     = h2pack(w4.x, w4.y);
            hbuf[r * 2 + 1] = h2pack(w4.z, w4.w);
        }
        *(uint4*)&Wt[0][wv * HPITCH + wq * 16]     = *(uint4*)&hbuf[0];
        *(uint4*)&Wt[0][wv * HPITCH + wq * 16 + 8] = *(uint4*)&hbuf[4];
        uint4 xr4 = *(const uint4*)(g_concat_h + (size_t)xb * H + xq * 8);
        *(uint4*)&Xt[0][xb * HPITCH + xq * 8] = xr4;
    }
    __syncthreads();

    for (int t = 0; t < NT; t++) {
        int cur = t & 1;
        float4 wpre[4];
        uint4 xpre;
        if (t + 1 < NT) {
            int kc = (t + 1) * KCL;
            const float* src = W + (size_t)(v0 + wv) * H + kc + wq * 16;
#pragma unroll
            for (int r = 0; r < 4; r++) wpre[r] = *(const float4*)(src + r * 4);
            xpre = *(const uint4*)(g_concat_h + (size_t)xb * H + kc + xq * 8);
        }

        // ---- compute on current buffer ----
#pragma unroll
        for (int ks = 0; ks < 2; ks++) {
            int kf = ks * 16;
            uint32_t a[2][4];
#pragma unroll
            for (int mf = 0; mf < 2; mf++) {
                int mm = warpM * 32 + mf * 16;
                const __half* p = &Wt[cur][(mm + (lane & 15)) * HPITCH + kf + ((lane >> 4) << 3)];
                ldsm_x4(a[mf], (uint32_t)__cvta_generic_to_shared(p));
            }
            uint32_t bf[4][2];
#pragma unroll
            for (int nf = 0; nf < 4; nf++) {
                int n = warpN * 32 + nf * 8;
                const __half* p = &Xt[cur][(n + (lane & 7)) * HPITCH + kf + (((lane >> 3) & 1) << 3)];
                ldsm_x2(bf[nf], (uint32_t)__cvta_generic_to_shared(p));
            }
#pragma unroll
            for (int nf = 0; nf < 4; nf++) {
                mma_f16(acc[0][nf], a[0], bf[nf][0], bf[nf][1]);
                mma_f16(acc[1][nf], a[1], bf[nf][0], bf[nf][1]);
            }
        }

        // ---- store prefetched tile ----
        if (t + 1 < NT) {
            int nxt = cur ^ 1;
            uint32_t hbuf[8];
#pragma unroll
            for (int r = 0; r < 4; r++) {
                hbuf[r * 2]     = h2pack(wpre[r].x, wpre[r].y);
                hbuf[r * 2 + 1] = h2pack(wpre[r].z, wpre[r].w);
            }
            *(uint4*)&Wt[nxt][wv * HPITCH + wq * 16]     = *(uint4*)&hbuf[0];
            *(uint4*)&Wt[nxt][wv * HPITCH + wq * 16 + 8] = *(uint4*)&hbuf[4];
            *(uint4*)&Xt[nxt][xb * HPITCH + xq * 8] = xpre;
        }
        __syncthreads();
    }

    // ---- epilogue (R12-validated mapping) ----
#pragma unroll
    for (int mf = 0; mf < 2; mf++) {
        int vr = v0 + warpM * 32 + mf * 16 + grp;
        float b0 = bias[vr], b1 = bias[vr + 8];
#pragma unroll
        for (int nf = 0; nf < 4; nf++) {
            int bcol = warpN * 32 + nf * 8 + 2 * tig;
            obase[(size_t)bcol * VP + vr]           = acc[mf][nf][0] + b0;
            obase[(size_t)(bcol + 1) * VP + vr]     = acc[mf][nf][1] + b0;
            obase[(size_t)bcol * VP + vr + 8]       = acc[mf][nf][2] + b1;
            obase[(size_t)(bcol + 1) * VP + vr + 8] = acc[mf][nf][3] + b1;
        }
    }
}

// ---------------------------------------------------------------------------
// attn-weights output softmax
// ---------------------------------------------------------------------------
__global__ void softmax_out_kernel(float* __restrict__ attn_out) {
    int b = blockIdx.x, tid = threadIdx.x;
    __shared__ float sh[8];
    __shared__ float sval;
    float m = -1e30f;
    for (int l = tid; l < L; l += 256) m = fmaxf(m, g_scores[b * L + l]);
#pragma unroll
    for (int o = 16; o; o >>= 1) m = fmaxf(m, __shfl_xor_sync(0xffffffffu, m, o));
    if ((tid & 31) == 0) sh[tid >> 5] = m;
    __syncthreads();
    if (tid == 0) {
        float mm = sh[0];
        for (int j = 1; j < 8; j++) mm = fmaxf(mm, sh[j]);
        sval = mm;
    }
    __syncthreads();
    m = sval;
    float s = 0.f;
    for (int l = tid; l < L; l += 256) s += expf(g_scores[b * L + l] - m);
    s = warp_sum(s);
    __syncthreads();
    if ((tid & 31) == 0) sh[tid >> 5] = s;
    __syncthreads();
    if (tid == 0) {
        float ss = 0.f;
        for (int j = 0; j < 8; j++) ss += sh[j];
        sval = ss;
    }
    __syncthreads();
    float inv = 1.f / sval;
    for (int l = tid; l < L; l += 256)
        attn_out[b * L + l] = expf(g_scores[b * L + l] - m) * inv;
}

// ---------------------------------------------------------------------------
extern "C" void kernel_launch(void* const* d_in, const int* in_sizes, int n_in,
                              void* d_out, int out_size) {
    const int*   seq         = (const int*)d_in[0];
    const float* last_hidden = (const float*)d_in[1];
    const float* enc         = (const float*)d_in[2];
    const float* emb         = (const float*)d_in[3];
    const float* w_ih        = (const float*)d_in[4];
    const float* w_hh        = (const float*)d_in[5];
    const float* b_ih        = (const float*)d_in[6];
    const float* b_hh        = (const float*)d_in[7];
    const float* concat_w    = (const float*)d_in[8];
    const float* concat_b    = (const float*)d_in[9];
    const float* owp         = (const float*)d_in[10];
    const float* obp         = (const float*)d_in[11];
    const float* owc         = (const float*)d_in[12];
    const float* obc         = (const float*)d_in[13];

    float* out        = (float*)d_out;
    float* out_hidden = out + (size_t)B * (VP + VC);
    float* out_attn   = out_hidden + (size_t)B * H;

    cudaFuncSetAttribute(gemm_part, cudaFuncAttributeMaxDynamicSharedMemorySize, SM_GEMM3);

    float* gatep; cudaGetSymbolAddress((void**)&gatep, g_gatep);
    float* xh;    cudaGetSymbolAddress((void**)&xh, g_xh);
    float* hc;    cudaGetSymbolAddress((void**)&hc, g_hc);
    float* cpart; cudaGetSymbolAddress((void**)&cpart, g_cpart);

    pack_xh_kernel<<<B, 256>>>(seq, last_hidden, emb);
    gemm_part<<<dim3(48, GRU_SPLITS), 256, SM_GEMM3>>>(
        w_ih, w_hh, xh, xh + (size_t)B * H, gatep,
        H, H / GRU_SPLITS, 24, GRU_ROWS);
    gru_gate_kernel<<<H / 4, 256>>>(last_hidden, b_ih, b_hh, out_hidden);
    flash2_kernel<<<dim3(B, CS), 256>>>(enc);          // 4th: profiled
    ctx_combine2_kernel<<<B, 256>>>();
    gemm_part<<<dim3(8, CAT_SPLITS), 256, SM_GEMM3>>>(
        concat_w, nullptr, hc, nullptr, cpart,
        2 * H, 2 * H / CAT_SPLITS, 0, CAT_ROWS);
    cat_reduce_kernel<<<H / 4, 256>>>(concat_b);
    logits_f16<<<(VP + VC) / TVL, 256>>>(owp, obp, owc, obc, out);
    softmax_out_kernel<<<B, 256>>>(out_attn);
}

// round 14
// speedup vs baseline: 1.0942x; 1.0942x over previous
#include <cuda_runtime.h>
#include <cuda_fp16.h>
#include <math.h>
#include <stdint.h>

#define H  1024
#define B  64
#define L  1024
#define VP 32000
#define VC 32000

// ---- flash attention config ----
#define CS   8
#define LPW  (L / CS / 8)
#define NPART 64

// ---- tf32 GEMM config (gru/concat) ----
#define TVL   128
#define KCL   32
#define PITCH 36
#define SM_GEMM3 ((2 * 2 * TVL * PITCH + 2 * 2 * B * PITCH) * 4)

// ---- logits fp16 GEMM: 2-stage, fp16 in smem ----
#define HPITCH 40
#define STG_HALVES (TVL * HPITCH + B * HPITCH)       // 7680 halves
#define SM_LOGF (2 * STG_HALVES * 2)                 // 30720 B... (2 stages)

#define GRU_ROWS   6144
#define GRU_SPLITS 2
#define CAT_ROWS   1024
#define CAT_SPLITS 4

// ---- scratch ----
__device__ __align__(16) float g_xh[2 * B * H];
__device__ __align__(16) float g_gatep[GRU_SPLITS * GRU_ROWS * B];
__device__ __align__(16) float g_hnew[B * H];
__device__ __align__(16) float g_hc[B * 2 * H];
__device__ __align__(16) float g_scores[B * L];
__device__ __align__(16) float g_ctxpart[B * NPART * H];
__device__ float g_pm[B * NPART];
__device__ float g_ps[B * NPART];
__device__ __align__(16) float g_cpart[CAT_SPLITS * CAT_ROWS * B];
__device__ __align__(16) __half g_concat_h[B * H];   // fp16 X for logits

__device__ __forceinline__ float warp_sum(float v) {
#pragma unroll
    for (int o = 16; o; o >>= 1) v += __shfl_xor_sync(0xffffffffu, v, o);
    return v;
}
__device__ __forceinline__ float f2tf32f(float x) {
    uint32_t u; asm("cvt.rna.tf32.f32 %0, %1;" : "=r"(u) : "f"(x));
    return __uint_as_float(u);
}
__device__ __forceinline__ void mma_tf32(float* c, const uint32_t* a,
                                         uint32_t b0, uint32_t b1) {
    asm volatile(
        "mma.sync.aligned.m16n8k8.row.col.f32.tf32.tf32.f32 "
        "{%0,%1,%2,%3}, {%4,%5,%6,%7}, {%8,%9}, {%0,%1,%2,%3};"
        : "+f"(c[0]), "+f"(c[1]), "+f"(c[2]), "+f"(c[3])
        : "r"(a[0]), "r"(a[1]), "r"(a[2]), "r"(a[3]), "r"(b0), "r"(b1));
}
__device__ __forceinline__ void mma_f16(float* c, const uint32_t* a,
                                        uint32_t b0, uint32_t b1) {
    asm volatile(
        "mma.sync.aligned.m16n8k16.row.col.f32.f16.f16.f32 "
        "{%0,%1,%2,%3}, {%4,%5,%6,%7}, {%8,%9}, {%0,%1,%2,%3};"
        : "+f"(c[0]), "+f"(c[1]), "+f"(c[2]), "+f"(c[3])
        : "r"(a[0]), "r"(a[1]), "r"(a[2]), "r"(a[3]), "r"(b0), "r"(b1));
}
// pack two fp32 into f16x2: lo in low half
__device__ __forceinline__ uint32_t h2pack(float lo, float hi) {
    uint32_t r; asm("cvt.rn.f16x2.f32 %0, %1, %2;" : "=r"(r) : "f"(hi), "f"(lo));
    return r;
}

// ---------------------------------------------------------------------------
// 0) pack x and h_prev
// ---------------------------------------------------------------------------
__global__ void pack_xh_kernel(const int* __restrict__ seq,
                               const float* __restrict__ hprev,
                               const float* __restrict__ emb) {
    int b = blockIdx.x, tid = threadIdx.x;
    ((float4*)(g_xh + (size_t)b * H))[tid] =
        ((const float4*)(emb + (size_t)seq[b] * H))[tid];
    ((float4*)(g_xh + (size_t)(B + b) * H))[tid] =
        ((const float4*)(hprev + (size_t)b * H))[tid];
}

// ---------------------------------------------------------------------------
// Generic SPLIT-3 tf32 GEMM (R10/R12, measured-good)
// ---------------------------------------------------------------------------
__global__ __launch_bounds__(256) void gemm_part(
        const float* __restrict__ A0, const float* __restrict__ A1,
        const float* __restrict__ X0, const float* __restrict__ X1,
        float* __restrict__ outp, int ldA, int kPerSplit, int halfBlocks,
        int totalRows) {
    extern __shared__ float smf[];
    float* Wt = smf;
    float* Xt = smf + 2 * 2 * TVL * PITCH;

    int tid = threadIdx.x;
    int wid = tid >> 5, lane = tid & 31;
    int grp = lane >> 2, tig = lane & 3;
    int warpM = wid & 3, warpN = wid >> 2;

    const float* A = A0; const float* X = X0;
    int blk = blockIdx.x;
    int outRowBase = blk * TVL;
    if (halfBlocks > 0 && blk >= halfBlocks) { A = A1; X = X1; blk -= halfBlocks; }
    int a0 = blk * TVL;
    int kOff = blockIdx.y * kPerSplit;
    int nt = kPerSplit / KCL;

#define WP_(buf, part) (Wt + ((buf) * 2 + (part)) * TVL * PITCH)
#define XP_(buf, part) (Xt + ((buf) * 2 + (part)) * B * PITCH)

    float acc[2][4][4];
#pragma unroll
    for (int i = 0; i < 2; i++)
#pragma unroll
        for (int j = 0; j < 4; j++)
#pragma unroll
            for (int q = 0; q < 4; q++) acc[i][j][q] = 0.f;

#pragma unroll
    for (int r = 0; r < 4; r++) {
        int f = tid + r * 256;
        int v = f >> 3, kq = f & 7;
        float4 w4 = *(const float4*)(A + (size_t)(a0 + v) * ldA + kOff + kq * 4);
        float hx = f2tf32f(w4.x), hy = f2tf32f(w4.y), hz = f2tf32f(w4.z), hw = f2tf32f(w4.w);
        *(float4*)&WP_(0, 0)[v * PITCH + kq * 4] = make_float4(hx, hy, hz, hw);
        *(float4*)&WP_(0, 1)[v * PITCH + kq * 4] =
            make_float4(f2tf32f(w4.x - hx), f2tf32f(w4.y - hy),
                        f2tf32f(w4.z - hz), f2tf32f(w4.w - hw));
    }
#pragma unroll
    for (int r = 0; r < 2; r++) {
        int f = tid + r * 256;
        int xb = f >> 3, kq = f & 7;
        float4 x4 = *(const float4*)(X + (size_t)xb * ldA + kOff + kq * 4);
        float hx = f2tf32f(x4.x), hy = f2tf32f(x4.y), hz = f2tf32f(x4.z), hw = f2tf32f(x4.w);
        *(float4*)&XP_(0, 0)[xb * PITCH + kq * 4] = make_float4(hx, hy, hz, hw);
        *(float4*)&XP_(0, 1)[xb * PITCH + kq * 4] =
            make_float4(f2tf32f(x4.x - hx), f2tf32f(x4.y - hy),
                        f2tf32f(x4.z - hz), f2tf32f(x4.w - hw));
    }
    __syncthreads();

    for (int t = 0; t < nt; t++) {
        int cur = t & 1;
        float* WH = WP_(cur, 0); float* WL = WP_(cur, 1);
        float* XH = XP_(cur, 0); float* XL = XP_(cur, 1);
        float4 wpre[4], xpre[2];
        if (t + 1 < nt) {
            int kc = kOff + (t + 1) * KCL;
#pragma unroll
            for (int r = 0; r < 4; r++) {
                int f = tid + r * 256;
                int v = f >> 3, kq = f & 7;
                wpre[r] = *(const float4*)(A + (size_t)(a0 + v) * ldA + kc + kq * 4);
            }
#pragma unroll
            for (int r = 0; r < 2; r++) {
                int f = tid + r * 256;
                int xb = f >> 3, kq = f & 7;
                xpre[r] = *(const float4*)(X + (size_t)xb * ldA + kc + kq * 4);
            }
        }
#pragma unroll
        for (int ks = 0; ks < KCL / 8; ks++) {
            int k0 = ks * 8 + tig;
            uint32_t aH[2][4], aL[2][4];
#pragma unroll
            for (int mf = 0; mf < 2; mf++) {
                int mm = warpM * 32 + mf * 16 + grp;
                aH[mf][0] = __float_as_uint(WH[mm * PITCH + k0]);
                aH[mf][1] = __float_as_uint(WH[(mm + 8) * PITCH + k0]);
                aH[mf][2] = __float_as_uint(WH[mm * PITCH + k0 + 4]);
                aH[mf][3] = __float_as_uint(WH[(mm + 8) * PITCH + k0 + 4]);
                aL[mf][0] = __float_as_uint(WL[mm * PITCH + k0]);
                aL[mf][1] = __float_as_uint(WL[(mm + 8) * PITCH + k0]);
                aL[mf][2] = __float_as_uint(WL[mm * PITCH + k0 + 4]);
                aL[mf][3] = __float_as_uint(WL[(mm + 8) * PITCH + k0 + 4]);
            }
#pragma unroll
            for (int nf = 0; nf < 4; nf++) {
                int n = warpN * 32 + nf * 8 + grp;
                uint32_t bH0 = __float_as_uint(XH[n * PITCH + k0]);
                uint32_t bH1 = __float_as_uint(XH[n * PITCH + k0 + 4]);
                uint32_t bL0 = __float_as_uint(XL[n * PITCH + k0]);
                uint32_t bL1 = __float_as_uint(XL[n * PITCH + k0 + 4]);
#pragma unroll
                for (int mf = 0; mf < 2; mf++) {
                    mma_tf32(acc[mf][nf], aH[mf], bH0, bH1);
                    mma_tf32(acc[mf][nf], aH[mf], bL0, bL1);
                    mma_tf32(acc[mf][nf], aL[mf], bH0, bH1);
                }
            }
        }
        if (t + 1 < nt) {
            int nxt = cur ^ 1;
#pragma unroll
            for (int r = 0; r < 4; r++) {
                int f = tid + r * 256;
                int v = f >> 3, kq = f & 7;
                float hx = f2tf32f(wpre[r].x), hy = f2tf32f(wpre[r].y);
                float hz = f2tf32f(wpre[r].z), hw = f2tf32f(wpre[r].w);
                *(float4*)&WP_(nxt, 0)[v * PITCH + kq * 4] = make_float4(hx, hy, hz, hw);
                *(float4*)&WP_(nxt, 1)[v * PITCH + kq * 4] =
                    make_float4(f2tf32f(wpre[r].x - hx), f2tf32f(wpre[r].y - hy),
                                f2tf32f(wpre[r].z - hz), f2tf32f(wpre[r].w - hw));
            }
#pragma unroll
            for (int r = 0; r < 2; r++) {
                int f = tid + r * 256;
                int xb = f >> 3, kq = f & 7;
                float hx = f2tf32f(xpre[r].x), hy = f2tf32f(xpre[r].y);
                float hz = f2tf32f(xpre[r].z), hw = f2tf32f(xpre[r].w);
                *(float4*)&XP_(nxt, 0)[xb * PITCH + kq * 4] = make_float4(hx, hy, hz, hw);
                *(float4*)&XP_(nxt, 1)[xb * PITCH + kq * 4] =
                    make_float4(f2tf32f(xpre[r].x - hx), f2tf32f(xpre[r].y - hy),
                                f2tf32f(xpre[r].z - hz), f2tf32f(xpre[r].w - hw));
            }
        }
        __syncthreads();
    }
#undef WP_
#undef XP_

    float* o = outp + (size_t)blockIdx.y * totalRows * B;
#pragma unroll
    for (int mf = 0; mf < 2; mf++) {
        int vr = outRowBase + warpM * 32 + mf * 16 + grp;
#pragma unroll
        for (int nf = 0; nf < 4; nf++) {
            int bcol = warpN * 32 + nf * 8 + 2 * tig;
            o[(size_t)vr * B + bcol]           = acc[mf][nf][0];
            o[(size_t)vr * B + bcol + 1]       = acc[mf][nf][1];
            o[(size_t)(vr + 8) * B + bcol]     = acc[mf][nf][2];
            o[(size_t)(vr + 8) * B + bcol + 1] = acc[mf][nf][3];
        }
    }
}

// ---------------------------------------------------------------------------
// gate combine -> h_new
// ---------------------------------------------------------------------------
__global__ void gru_gate_kernel(const float* __restrict__ hprev,
                                const float* __restrict__ b_ih,
                                const float* __restrict__ b_hh,
                                float* __restrict__ hidden_out) {
    int tid = threadIdx.x;
    int b = tid & 63;
    int i = blockIdx.x * 4 + (tid >> 6);
#define GP(row) (g_gatep[(size_t)(row) * B + b] + \
                 g_gatep[(size_t)(GRU_ROWS + (row)) * B + b])
    float gir = GP(i),          giz = GP(H + i),      gin = GP(2 * H + i);
    float ghr = GP(3 * H + i),  ghz = GP(4 * H + i),  ghn = GP(5 * H + i);
#undef GP
    float r = 1.f / (1.f + expf(-(gir + b_ih[i] + ghr + b_hh[i])));
    float z = 1.f / (1.f + expf(-(giz + b_ih[H + i] + ghz + b_hh[H + i])));
    float n = tanhf(gin + b_ih[2 * H + i] + r * (ghn + b_hh[2 * H + i]));
    float hv = hprev[(size_t)b * H + i];
    float hn = (1.f - z) * n + z * hv;
    g_hnew[(size_t)b * H + i] = hn;
    g_hc[(size_t)b * 2 * H + i] = hn;
    hidden_out[(size_t)b * H + i] = hn;
}

// ---------------------------------------------------------------------------
// flash attention (measured 46.5us @ 77% DRAM)
// ---------------------------------------------------------------------------
__global__ __launch_bounds__(256) void flash2_kernel(const float* __restrict__ enc) {
    int b = blockIdx.x, ch = blockIdx.y;
    int w = threadIdx.x >> 5, lane = threadIdx.x & 31;
    int l0 = ch * (L / CS) + w * LPW;

    const float4* hb = (const float4*)(g_hnew + (size_t)b * H);
    float4 h[8];
#pragma unroll
    for (int q = 0; q < 8; q++) h[q] = hb[lane + q * 32];

    float4 acc[8];
#pragma unroll
    for (int q = 0; q < 8; q++) acc[q] = make_float4(0.f, 0.f, 0.f, 0.f);
    float m = -1e30f, ssum = 0.f;

    for (int j = 0; j < LPW; j++) {
        int l = l0 + j;
        const float4* er = (const float4*)(enc + ((size_t)l * B + b) * H);
        float4 e[8];
        float d = 0.f;
#pragma unroll
        for (int q = 0; q < 8; q++) {
            e[q] = er[lane + q * 32];
            d += e[q].x * h[q].x + e[q].y * h[q].y + e[q].z * h[q].z + e[q].w * h[q].w;
        }
        d = warp_sum(d);
        if (lane == 0) g_scores[b * L + l] = d;
        float nm = fmaxf(m, d);
        float sc = expf(m - nm);
        float p = expf(d - nm);
        ssum = ssum * sc + p;
#pragma unroll
        for (int q = 0; q < 8; q++) {
            acc[q].x = acc[q].x * sc + p * e[q].x;
            acc[q].y = acc[q].y * sc + p * e[q].y;
            acc[q].z = acc[q].z * sc + p * e[q].z;
            acc[q].w = acc[q].w * sc + p * e[q].w;
        }
        m = nm;
    }

    int pidx = b * NPART + ch * 8 + w;
    float4* pp = (float4*)(g_ctxpart + (size_t)pidx * H);
#pragma unroll
    for (int q = 0; q < 8; q++) pp[lane + q * 32] = acc[q];
    if (lane == 0) { g_pm[pidx] = m; g_ps[pidx] = ssum; }
}

__global__ void ctx_combine2_kernel() {
    int b = blockIdx.x, tid = threadIdx.x;
    __shared__ float sm[NPART], sw[NPART];
    if (tid < NPART) sm[tid] = g_pm[b * NPART + tid];
    __syncthreads();
    float gm = -1e30f;
#pragma unroll 8
    for (int c = 0; c < NPART; c++) gm = fmaxf(gm, sm[c]);
    if (tid < NPART) sw[tid] = expf(sm[tid] - gm);
    __syncthreads();
    float S = 0.f;
#pragma unroll 8
    for (int c = 0; c < NPART; c++) S += g_ps[b * NPART + c] * sw[c];
    float inv = 1.f / S;
    float4 a = make_float4(0.f, 0.f, 0.f, 0.f);
    for (int c = 0; c < NPART; c++) {
        float wgt = sw[c];
        float4 p = ((const float4*)(g_ctxpart + ((size_t)(b * NPART + c)) * H))[tid];
        a.x += wgt * p.x; a.y += wgt * p.y; a.z += wgt * p.z; a.w += wgt * p.w;
    }
    a.x *= inv; a.y *= inv; a.z *= inv; a.w *= inv;
    ((float4*)(g_hc + (size_t)b * 2 * H + H))[tid] = a;
}

// ---------------------------------------------------------------------------
// concat reduce + tanh -> g_concat_h (fp16)
// ---------------------------------------------------------------------------
__global__ void cat_reduce_kernel(const float* __restrict__ cb) {
    int tid = threadIdx.x;
    int b = tid & 63;
    int i = blockIdx.x * 4 + (tid >> 6);
    float s = 0.f;
#pragma unroll
    for (int y = 0; y < CAT_SPLITS; y++)
        s += g_cpart[(size_t)(y * CAT_ROWS + i) * B + b];
    g_concat_h[(size_t)b * H + i] = __float2half_rn(tanhf(s + cb[i]));
}

// ---------------------------------------------------------------------------
// logits: fp16 m16n8k16 GEMM. 2-stage fp16-in-smem double buffer with
// register prefetch (R12 loader pattern, coalesced 128B/8 threads).
// Scalar LDS.32 fragment loads (R12-validated mapping), zero per-tile cvts.
// 51.2 KB smem -> 4 blocks/SM -> all 500 blocks resident in one wave.
// ---------------------------------------------------------------------------
__global__ __launch_bounds__(256) void logits_f16(
        const float* __restrict__ wp, const float* __restrict__ bp,
        const float* __restrict__ wc, const float* __restrict__ bc,
        float* __restrict__ out) {
    extern __shared__ __half smh[];
    __half* Wt = smh;                         // [2][TVL * HPITCH]
    __half* Xt = smh + 2 * TVL * HPITCH;      // [2][B * HPITCH]

    int tid = threadIdx.x;
    int wid = tid >> 5, lane = tid & 31;
    int grp = lane >> 2, tig = lane & 3;
    int warpM = wid & 3, warpN = wid >> 2;

    int v0 = blockIdx.x * TVL;
    const float* W; const float* bias; float* obase;
    if (v0 < VP) { W = wp; bias = bp; obase = out; }
    else { W = wc; bias = bc; obase = out + (size_t)B * VP; v0 -= VP; }

    float acc[2][4][4];
#pragma unroll
    for (int i = 0; i < 2; i++)
#pragma unroll
        for (int j = 0; j < 4; j++)
#pragma unroll
            for (int q = 0; q < 4; q++) acc[i][j][q] = 0.f;

    const int NT = H / KCL;   // 32
    int xb = tid >> 2, xq = tid & 3;

    // ---- prime buffer 0 ----
    {
#pragma unroll
        for (int r = 0; r < 4; r++) {
            int f = tid + r * 256;
            int v = f >> 3, kq = f & 7;          // coalesced: 8 thr = 128B of row v
            float4 w4 = *(const float4*)(W + (size_t)(v0 + v) * H + kq * 4);
            uint32_t p0 = h2pack(w4.x, w4.y), p1 = h2pack(w4.z, w4.w);
            *(uint2*)&Wt[v * HPITCH + kq * 4] = make_uint2(p0, p1);
        }
        uint4 x4 = *(const uint4*)(g_concat_h + (size_t)xb * H + xq * 8);
        *(uint4*)&Xt[xb * HPITCH + xq * 8] = x4;
    }
    __syncthreads();

    for (int t = 0; t < NT; t++) {
        int cur = t & 1;
        __half* Wc = Wt + cur * TVL * HPITCH;
        __half* Xc = Xt + cur * B * HPITCH;
        float4 wpre[4];
        uint4 xpre;
        if (t + 1 < NT) {
            int kc = (t + 1) * KCL;
#pragma unroll
            for (int r = 0; r < 4; r++) {
                int f = tid + r * 256;
                int v = f >> 3, kq = f & 7;
                wpre[r] = *(const float4*)(W + (size_t)(v0 + v) * H + kc + kq * 4);
            }
            xpre = *(const uint4*)(g_concat_h + (size_t)xb * H + kc + xq * 8);
        }

        // ---- compute current tile (R12 mapping, fp16 smem) ----
#pragma unroll
        for (int ks = 0; ks < 2; ks++) {
            int kf = ks * 16 + 2 * tig;
            uint32_t a[2][4];
#pragma unroll
            for (int mf = 0; mf < 2; mf++) {
                int mm = warpM * 32 + mf * 16 + grp;
                a[mf][0] = *(const uint32_t*)&Wc[mm * HPITCH + kf];
                a[mf][1] = *(const uint32_t*)&Wc[(mm + 8) * HPITCH + kf];
                a[mf][2] = *(const uint32_t*)&Wc[mm * HPITCH + kf + 8];
                a[mf][3] = *(const uint32_t*)&Wc[(mm + 8) * HPITCH + kf + 8];
            }
#pragma unroll
            for (int nf = 0; nf < 4; nf++) {
                int n = warpN * 32 + nf * 8 + grp;
                uint32_t b0 = *(const uint32_t*)&Xc[n * HPITCH + kf];
                uint32_t b1 = *(const uint32_t*)&Xc[n * HPITCH + kf + 8];
                mma_f16(acc[0][nf], a[0], b0, b1);
                mma_f16(acc[1][nf], a[1], b0, b1);
            }
        }

        // ---- store prefetched tile ----
        if (t + 1 < NT) {
            __half* Wn = Wt + (cur ^ 1) * TVL * HPITCH;
            __half* Xn = Xt + (cur ^ 1) * B * HPITCH;
#pragma unroll
            for (int r = 0; r < 4; r++) {
                int f = tid + r * 256;
                int v = f >> 3, kq = f & 7;
                uint32_t p0 = h2pack(wpre[r].x, wpre[r].y);
                uint32_t p1 = h2pack(wpre[r].z, wpre[r].w);
                *(uint2*)&Wn[v * HPITCH + kq * 4] = make_uint2(p0, p1);
            }
            *(uint4*)&Xn[xb * HPITCH + xq * 8] = xpre;
        }
        __syncthreads();
    }

    // ---- epilogue (R12-validated mapping) ----
#pragma unroll
    for (int mf = 0; mf < 2; mf++) {
        int vr = v0 + warpM * 32 + mf * 16 + grp;
        float b0 = bias[vr], b1 = bias[vr + 8];
#pragma unroll
        for (int nf = 0; nf < 4; nf++) {
            int bcol = warpN * 32 + nf * 8 + 2 * tig;
            obase[(size_t)bcol * VP + vr]           = acc[mf][nf][0] + b0;
            obase[(size_t)(bcol + 1) * VP + vr]     = acc[mf][nf][1] + b0;
            obase[(size_t)bcol * VP + vr + 8]       = acc[mf][nf][2] + b1;
            obase[(size_t)(bcol + 1) * VP + vr + 8] = acc[mf][nf][3] + b1;
        }
    }
}

// ---------------------------------------------------------------------------
// attn-weights output softmax
// ---------------------------------------------------------------------------
__global__ void softmax_out_kernel(float* __restrict__ attn_out) {
    int b = blockIdx.x, tid = threadIdx.x;
    __shared__ float sh[8];
    __shared__ float sval;
    float m = -1e30f;
    for (int l = tid; l < L; l += 256) m = fmaxf(m, g_scores[b * L + l]);
#pragma unroll
    for (int o = 16; o; o >>= 1) m = fmaxf(m, __shfl_xor_sync(0xffffffffu, m, o));
    if ((tid & 31) == 0) sh[tid >> 5] = m;
    __syncthreads();
    if (tid == 0) {
        float mm = sh[0];
        for (int j = 1; j < 8; j++) mm = fmaxf(mm, sh[j]);
        sval = mm;
    }
    __syncthreads();
    m = sval;
    float s = 0.f;
    for (int l = tid; l < L; l += 256) s += expf(g_scores[b * L + l] - m);
    s = warp_sum(s);
    __syncthreads();
    if ((tid & 31) == 0) sh[tid >> 5] = s;
    __syncthreads();
    if (tid == 0) {
        float ss = 0.f;
        for (int j = 0; j < 8; j++) ss += sh[j];
        sval = ss;
    }
    __syncthreads();
    float inv = 1.f / sval;
    for (int l = tid; l < L; l += 256)
        attn_out[b * L + l] = expf(g_scores[b * L + l] - m) * inv;
}

// ---------------------------------------------------------------------------
extern "C" void kernel_launch(void* const* d_in, const int* in_sizes, int n_in,
                              void* d_out, int out_size) {
    const int*   seq         = (const int*)d_in[0];
    const float* last_hidden = (const float*)d_in[1];
    const float* enc         = (const float*)d_in[2];
    const float* emb         = (const float*)d_in[3];
    const float* w_ih        = (const float*)d_in[4];
    const float* w_hh        = (const float*)d_in[5];
    const float* b_ih        = (const float*)d_in[6];
    const float* b_hh        = (const float*)d_in[7];
    const float* concat_w    = (const float*)d_in[8];
    const float* concat_b    = (const float*)d_in[9];
    const float* owp         = (const float*)d_in[10];
    const float* obp         = (const float*)d_in[11];
    const float* owc         = (const float*)d_in[12];
    const float* obc         = (const float*)d_in[13];

    float* out        = (float*)d_out;
    float* out_hidden = out + (size_t)B * (VP + VC);
    float* out_attn   = out_hidden + (size_t)B * H;

    cudaFuncSetAttribute(gemm_part,  cudaFuncAttributeMaxDynamicSharedMemorySize, SM_GEMM3);
    cudaFuncSetAttribute(logits_f16, cudaFuncAttributeMaxDynamicSharedMemorySize, SM_LOGF);

    float* gatep; cudaGetSymbolAddress((void**)&gatep, g_gatep);
    float* xh;    cudaGetSymbolAddress((void**)&xh, g_xh);
    float* hc;    cudaGetSymbolAddress((void**)&hc, g_hc);
    float* cpart; cudaGetSymbolAddress((void**)&cpart, g_cpart);

    pack_xh_kernel<<<B, 256>>>(seq, last_hidden, emb);
    gemm_part<<<dim3(48, GRU_SPLITS), 256, SM_GEMM3>>>(
        w_ih, w_hh, xh, xh + (size_t)B * H, gatep,
        H, H / GRU_SPLITS, 24, GRU_ROWS);
    gru_gate_kernel<<<H / 4, 256>>>(last_hidden, b_ih, b_hh, out_hidden);
    flash2_kernel<<<dim3(B, CS), 256>>>(enc);          // 4th: profiled
    ctx_combine2_kernel<<<B, 256>>>();
    gemm_part<<<dim3(8, CAT_SPLITS), 256, SM_GEMM3>>>(
        concat_w, nullptr, hc, nullptr, cpart,
        2 * H, 2 * H / CAT_SPLITS, 0, CAT_ROWS);
    cat_reduce_kernel<<<H / 4, 256>>>(concat_b);
    logits_f16<<<(VP + VC) / TVL, 256, SM_LOGF>>>(owp, obp, owc, obc, out);
    softmax_out_kernel<<<B, 256>>>(out_attn);
}

// round 15
// speedup vs baseline: 1.1625x; 1.0624x over previous
#include <cuda_runtime.h>
#include <cuda_fp16.h>
#include <math.h>
#include <stdint.h>

#define H  1024
#define B  64
#define L  1024
#define VP 32000
#define VC 32000

// ---- flash attention config ----
#define CS   8
#define LPW  (L / CS / 8)
#define NPART 64

// ---- shared GEMM tile config ----
#define TVL   128
#define KCL   32
#define HPITCH 40     // halves per row (80B rows: conflict-free scalar frags)

// split-2 fp16 gemm (gru/cat): 2 buf x 2 parts x (W 128x40 + X 64x40) halves
#define SM_G16 ((2 * 2 * TVL * HPITCH + 2 * 2 * B * HPITCH) * 2)   // 61440 B
// logits fp16 gemm: 2 buf x (W + X)
#define SM_LOGF ((2 * TVL * HPITCH + 2 * B * HPITCH) * 2)          // 30720 B

#define GRU_ROWS   6144
#define GRU_SPLITS 2
#define CAT_ROWS   1024
#define CAT_SPLITS 4

// ---- scratch ----
__device__ __align__(16) float g_xh[2 * B * H];
__device__ __align__(16) float g_gatep[GRU_SPLITS * GRU_ROWS * B];
__device__ __align__(16) float g_hnew[B * H];
__device__ __align__(16) float g_hc[B * 2 * H];
__device__ __align__(16) float g_scores[B * L];
__device__ __align__(16) float g_ctxpart[B * NPART * H];
__device__ float g_pm[B * NPART];
__device__ float g_ps[B * NPART];
__device__ __align__(16) float g_cpart[CAT_SPLITS * CAT_ROWS * B];
__device__ __align__(16) __half g_concat_h[B * H];

__device__ __forceinline__ float warp_sum(float v) {
#pragma unroll
    for (int o = 16; o; o >>= 1) v += __shfl_xor_sync(0xffffffffu, v, o);
    return v;
}
__device__ __forceinline__ void mma_f16(float* c, const uint32_t* a,
                                        uint32_t b0, uint32_t b1) {
    asm volatile(
        "mma.sync.aligned.m16n8k16.row.col.f32.f16.f16.f32 "
        "{%0,%1,%2,%3}, {%4,%5,%6,%7}, {%8,%9}, {%0,%1,%2,%3};"
        : "+f"(c[0]), "+f"(c[1]), "+f"(c[2]), "+f"(c[3])
        : "r"(a[0]), "r"(a[1]), "r"(a[2]), "r"(a[3]), "r"(b0), "r"(b1));
}
__device__ __forceinline__ uint32_t h2pack(float lo, float hi) {
    uint32_t r; asm("cvt.rn.f16x2.f32 %0, %1, %2;" : "=r"(r) : "f"(hi), "f"(lo));
    return r;
}
// split one fp32 into hi/lo fp16 halves
__device__ __forceinline__ void hsplit(float x, __half& hi, __half& lo) {
    hi = __float2half_rn(x);
    lo = __float2half_rn(x - __half2float(hi));
}

// ---------------------------------------------------------------------------
// 0) pack x and h_prev
// ---------------------------------------------------------------------------
__global__ void pack_xh_kernel(const int* __restrict__ seq,
                               const float* __restrict__ hprev,
                               const float* __restrict__ emb) {
    int b = blockIdx.x, tid = threadIdx.x;
    ((float4*)(g_xh + (size_t)b * H))[tid] =
        ((const float4*)(emb + (size_t)seq[b] * H))[tid];
    ((float4*)(g_xh + (size_t)(B + b) * H))[tid] =
        ((const float4*)(hprev + (size_t)b * H))[tid];
}

// ---------------------------------------------------------------------------
// Generic SPLIT-2 fp16 k16 GEMM (fp32-accurate), split-K, raw-partial out.
// D = Whi*Xhi + Whi*Xlo + Wlo*Xhi   (fp32 accum; lo*lo ~2^-22 dropped)
// Block = 128 rows x 64 batch, 8 warps (4Mx2N), KCL=32 double-buffered.
// Compute fragment mapping identical to the validated logits_f16 kernel.
// ---------------------------------------------------------------------------
__global__ __launch_bounds__(256) void gemm_part(
        const float* __restrict__ A0, const float* __restrict__ A1,
        const float* __restrict__ X0, const float* __restrict__ X1,
        float* __restrict__ outp, int ldA, int kPerSplit, int halfBlocks,
        int totalRows) {
    extern __shared__ __half smh[];
    __half* Wt = smh;                                  // [buf][part][TVL*HPITCH]
    __half* Xt = smh + 2 * 2 * TVL * HPITCH;           // [buf][part][B*HPITCH]

    int tid = threadIdx.x;
    int wid = tid >> 5, lane = tid & 31;
    int grp = lane >> 2, tig = lane & 3;
    int warpM = wid & 3, warpN = wid >> 2;

    const float* A = A0; const float* X = X0;
    int blk = blockIdx.x;
    int outRowBase = blk * TVL;
    if (halfBlocks > 0 && blk >= halfBlocks) { A = A1; X = X1; blk -= halfBlocks; }
    int a0 = blk * TVL;
    int kOff = blockIdx.y * kPerSplit;
    int nt = kPerSplit / KCL;

#define WPH(buf, part) (Wt + ((buf) * 2 + (part)) * TVL * HPITCH)
#define XPH(buf, part) (Xt + ((buf) * 2 + (part)) * B * HPITCH)

    float acc[2][4][4];
#pragma unroll
    for (int i = 0; i < 2; i++)
#pragma unroll
        for (int j = 0; j < 4; j++)
#pragma unroll
            for (int q = 0; q < 4; q++) acc[i][j][q] = 0.f;

    // loader helper: convert float4 -> hi/lo uint2 and store
    auto storeW = [&](int buf, int v, int kq, float4 w4) {
        __half hx, lx, hy, ly, hz, lz, hw, lw;
        hsplit(w4.x, hx, lx); hsplit(w4.y, hy, ly);
        hsplit(w4.z, hz, lz); hsplit(w4.w, hw, lw);
        *(uint2*)&WPH(buf, 0)[v * HPITCH + kq * 4] =
            make_uint2(h2pack(__half2float(hx), __half2float(hy)),
                       h2pack(__half2float(hz), __half2float(hw)));
        *(uint2*)&WPH(buf, 1)[v * HPITCH + kq * 4] =
            make_uint2(h2pack(__half2float(lx), __half2float(ly)),
                       h2pack(__half2float(lz), __half2float(lw)));
    };
    auto storeX = [&](int buf, int xb, int kq, float4 x4) {
        __half hx, lx, hy, ly, hz, lz, hw, lw;
        hsplit(x4.x, hx, lx); hsplit(x4.y, hy, ly);
        hsplit(x4.z, hz, lz); hsplit(x4.w, hw, lw);
        *(uint2*)&XPH(buf, 0)[xb * HPITCH + kq * 4] =
            make_uint2(h2pack(__half2float(hx), __half2float(hy)),
                       h2pack(__half2float(hz), __half2float(hw)));
        *(uint2*)&XPH(buf, 1)[xb * HPITCH + kq * 4] =
            make_uint2(h2pack(__half2float(lx), __half2float(ly)),
                       h2pack(__half2float(lz), __half2float(lw)));
    };

    // ---- prime buffer 0 ----
#pragma unroll
    for (int r = 0; r < 4; r++) {
        int f = tid + r * 256;
        int v = f >> 3, kq = f & 7;
        float4 w4 = *(const float4*)(A + (size_t)(a0 + v) * ldA + kOff + kq * 4);
        storeW(0, v, kq, w4);
    }
#pragma unroll
    for (int r = 0; r < 2; r++) {
        int f = tid + r * 256;
        int xb = f >> 3, kq = f & 7;
        float4 x4 = *(const float4*)(X + (size_t)xb * ldA + kOff + kq * 4);
        storeX(0, xb, kq, x4);
    }
    __syncthreads();

    for (int t = 0; t < nt; t++) {
        int cur = t & 1;
        __half* WH = WPH(cur, 0); __half* WL = WPH(cur, 1);
        __half* XH = XPH(cur, 0); __half* XL = XPH(cur, 1);
        float4 wpre[4], xpre[2];
        if (t + 1 < nt) {
            int kc = kOff + (t + 1) * KCL;
#pragma unroll
            for (int r = 0; r < 4; r++) {
                int f = tid + r * 256;
                int v = f >> 3, kq = f & 7;
                wpre[r] = *(const float4*)(A + (size_t)(a0 + v) * ldA + kc + kq * 4);
            }
#pragma unroll
            for (int r = 0; r < 2; r++) {
                int f = tid + r * 256;
                int xb = f >> 3, kq = f & 7;
                xpre[r] = *(const float4*)(X + (size_t)xb * ldA + kc + kq * 4);
            }
        }

        // ---- compute current tile: 2 k16 steps ----
#pragma unroll
        for (int ks = 0; ks < 2; ks++) {
            int kf = ks * 16 + 2 * tig;
            uint32_t aH[2][4], aL[2][4];
#pragma unroll
            for (int mf = 0; mf < 2; mf++) {
                int mm = warpM * 32 + mf * 16 + grp;
                aH[mf][0] = *(const uint32_t*)&WH[mm * HPITCH + kf];
                aH[mf][1] = *(const uint32_t*)&WH[(mm + 8) * HPITCH + kf];
                aH[mf][2] = *(const uint32_t*)&WH[mm * HPITCH + kf + 8];
                aH[mf][3] = *(const uint32_t*)&WH[(mm + 8) * HPITCH + kf + 8];
                aL[mf][0] = *(const uint32_t*)&WL[mm * HPITCH + kf];
                aL[mf][1] = *(const uint32_t*)&WL[(mm + 8) * HPITCH + kf];
                aL[mf][2] = *(const uint32_t*)&WL[mm * HPITCH + kf + 8];
                aL[mf][3] = *(const uint32_t*)&WL[(mm + 8) * HPITCH + kf + 8];
            }
#pragma unroll
            for (int nf = 0; nf < 4; nf++) {
                int n = warpN * 32 + nf * 8 + grp;
                uint32_t bH0 = *(const uint32_t*)&XH[n * HPITCH + kf];
                uint32_t bH1 = *(const uint32_t*)&XH[n * HPITCH + kf + 8];
                uint32_t bL0 = *(const uint32_t*)&XL[n * HPITCH + kf];
                uint32_t bL1 = *(const uint32_t*)&XL[n * HPITCH + kf + 8];
#pragma unroll
                for (int mf = 0; mf < 2; mf++) {
                    mma_f16(acc[mf][nf], aH[mf], bH0, bH1);
                    mma_f16(acc[mf][nf], aH[mf], bL0, bL1);
                    mma_f16(acc[mf][nf], aL[mf], bH0, bH1);
                }
            }
        }

        // ---- store prefetched tile ----
        if (t + 1 < nt) {
            int nxt = cur ^ 1;
#pragma unroll
            for (int r = 0; r < 4; r++) {
                int f = tid + r * 256;
                int v = f >> 3, kq = f & 7;
                storeW(nxt, v, kq, wpre[r]);
            }
#pragma unroll
            for (int r = 0; r < 2; r++) {
                int f = tid + r * 256;
                int xb = f >> 3, kq = f & 7;
                storeX(nxt, xb, kq, xpre[r]);
            }
        }
        __syncthreads();
    }
#undef WPH
#undef XPH

    float* o = outp + (size_t)blockIdx.y * totalRows * B;
#pragma unroll
    for (int mf = 0; mf < 2; mf++) {
        int vr = outRowBase + warpM * 32 + mf * 16 + grp;
#pragma unroll
        for (int nf = 0; nf < 4; nf++) {
            int bcol = warpN * 32 + nf * 8 + 2 * tig;
            o[(size_t)vr * B + bcol]           = acc[mf][nf][0];
            o[(size_t)vr * B + bcol + 1]       = acc[mf][nf][1];
            o[(size_t)(vr + 8) * B + bcol]     = acc[mf][nf][2];
            o[(size_t)(vr + 8) * B + bcol + 1] = acc[mf][nf][3];
        }
    }
}

// ---------------------------------------------------------------------------
// gate combine -> h_new
// ---------------------------------------------------------------------------
__global__ void gru_gate_kernel(const float* __restrict__ hprev,
                                const float* __restrict__ b_ih,
                                const float* __restrict__ b_hh,
                                float* __restrict__ hidden_out) {
    int tid = threadIdx.x;
    int b = tid & 63;
    int i = blockIdx.x * 4 + (tid >> 6);
#define GP(row) (g_gatep[(size_t)(row) * B + b] + \
                 g_gatep[(size_t)(GRU_ROWS + (row)) * B + b])
    float gir = GP(i),          giz = GP(H + i),      gin = GP(2 * H + i);
    float ghr = GP(3 * H + i),  ghz = GP(4 * H + i),  ghn = GP(5 * H + i);
#undef GP
    float r = 1.f / (1.f + expf(-(gir + b_ih[i] + ghr + b_hh[i])));
    float z = 1.f / (1.f + expf(-(giz + b_ih[H + i] + ghz + b_hh[H + i])));
    float n = tanhf(gin + b_ih[2 * H + i] + r * (ghn + b_hh[2 * H + i]));
    float hv = hprev[(size_t)b * H + i];
    float hn = (1.f - z) * n + z * hv;
    g_hnew[(size_t)b * H + i] = hn;
    g_hc[(size_t)b * 2 * H + i] = hn;
    hidden_out[(size_t)b * H + i] = hn;
}

// ---------------------------------------------------------------------------
// flash attention (measured-good)
// ---------------------------------------------------------------------------
__global__ __launch_bounds__(256) void flash2_kernel(const float* __restrict__ enc) {
    int b = blockIdx.x, ch = blockIdx.y;
    int w = threadIdx.x >> 5, lane = threadIdx.x & 31;
    int l0 = ch * (L / CS) + w * LPW;

    const float4* hb = (const float4*)(g_hnew + (size_t)b * H);
    float4 h[8];
#pragma unroll
    for (int q = 0; q < 8; q++) h[q] = hb[lane + q * 32];

    float4 acc[8];
#pragma unroll
    for (int q = 0; q < 8; q++) acc[q] = make_float4(0.f, 0.f, 0.f, 0.f);
    float m = -1e30f, ssum = 0.f;

    for (int j = 0; j < LPW; j++) {
        int l = l0 + j;
        const float4* er = (const float4*)(enc + ((size_t)l * B + b) * H);
        float4 e[8];
        float d = 0.f;
#pragma unroll
        for (int q = 0; q < 8; q++) {
            e[q] = er[lane + q * 32];
            d += e[q].x * h[q].x + e[q].y * h[q].y + e[q].z * h[q].z + e[q].w * h[q].w;
        }
        d = warp_sum(d);
        if (lane == 0) g_scores[b * L + l] = d;
        float nm = fmaxf(m, d);
        float sc = expf(m - nm);
        float p = expf(d - nm);
        ssum = ssum * sc + p;
#pragma unroll
        for (int q = 0; q < 8; q++) {
            acc[q].x = acc[q].x * sc + p * e[q].x;
            acc[q].y = acc[q].y * sc + p * e[q].y;
            acc[q].z = acc[q].z * sc + p * e[q].z;
            acc[q].w = acc[q].w * sc + p * e[q].w;
        }
        m = nm;
    }

    int pidx = b * NPART + ch * 8 + w;
    float4* pp = (float4*)(g_ctxpart + (size_t)pidx * H);
#pragma unroll
    for (int q = 0; q < 8; q++) pp[lane + q * 32] = acc[q];
    if (lane == 0) { g_pm[pidx] = m; g_ps[pidx] = ssum; }
}

__global__ void ctx_combine2_kernel() {
    int b = blockIdx.x, tid = threadIdx.x;
    __shared__ float sm[NPART], sw[NPART];
    if (tid < NPART) sm[tid] = g_pm[b * NPART + tid];
    __syncthreads();
    float gm = -1e30f;
#pragma unroll 8
    for (int c = 0; c < NPART; c++) gm = fmaxf(gm, sm[c]);
    if (tid < NPART) sw[tid] = expf(sm[tid] - gm);
    __syncthreads();
    float S = 0.f;
#pragma unroll 8
    for (int c = 0; c < NPART; c++) S += g_ps[b * NPART + c] * sw[c];
    float inv = 1.f / S;
    float4 a = make_float4(0.f, 0.f, 0.f, 0.f);
    for (int c = 0; c < NPART; c++) {
        float wgt = sw[c];
        float4 p = ((const float4*)(g_ctxpart + ((size_t)(b * NPART + c)) * H))[tid];
        a.x += wgt * p.x; a.y += wgt * p.y; a.z += wgt * p.z; a.w += wgt * p.w;
    }
    a.x *= inv; a.y *= inv; a.z *= inv; a.w *= inv;
    ((float4*)(g_hc + (size_t)b * 2 * H + H))[tid] = a;
}

// ---------------------------------------------------------------------------
// concat reduce + tanh -> g_concat_h (fp16)
// ---------------------------------------------------------------------------
__global__ void cat_reduce_kernel(const float* __restrict__ cb) {
    int tid = threadIdx.x;
    int b = tid & 63;
    int i = blockIdx.x * 4 + (tid >> 6);
    float s = 0.f;
#pragma unroll
    for (int y = 0; y < CAT_SPLITS; y++)
        s += g_cpart[(size_t)(y * CAT_ROWS + i) * B + b];
    g_concat_h[(size_t)b * H + i] = __float2half_rn(tanhf(s + cb[i]));
}

// ---------------------------------------------------------------------------
// logits: fp16 m16n8k16 GEMM, 2-stage fp16-in-smem (R14, measured-good)
// ---------------------------------------------------------------------------
__global__ __launch_bounds__(256) void logits_f16(
        const float* __restrict__ wp, const float* __restrict__ bp,
        const float* __restrict__ wc, const float* __restrict__ bc,
        float* __restrict__ out) {
    extern __shared__ __half smh[];
    __half* Wt = smh;
    __half* Xt = smh + 2 * TVL * HPITCH;

    int tid = threadIdx.x;
    int wid = tid >> 5, lane = tid & 31;
    int grp = lane >> 2, tig = lane & 3;
    int warpM = wid & 3, warpN = wid >> 2;

    int v0 = blockIdx.x * TVL;
    const float* W; const float* bias; float* obase;
    if (v0 < VP) { W = wp; bias = bp; obase = out; }
    else { W = wc; bias = bc; obase = out + (size_t)B * VP; v0 -= VP; }

    float acc[2][4][4];
#pragma unroll
    for (int i = 0; i < 2; i++)
#pragma unroll
        for (int j = 0; j < 4; j++)
#pragma unroll
            for (int q = 0; q < 4; q++) acc[i][j][q] = 0.f;

    const int NT = H / KCL;
    int xb = tid >> 2, xq = tid & 3;

    {
#pragma unroll
        for (int r = 0; r < 4; r++) {
            int f = tid + r * 256;
            int v = f >> 3, kq = f & 7;
            float4 w4 = *(const float4*)(W + (size_t)(v0 + v) * H + kq * 4);
            uint32_t p0 = h2pack(w4.x, w4.y), p1 = h2pack(w4.z, w4.w);
            *(uint2*)&Wt[v * HPITCH + kq * 4] = make_uint2(p0, p1);
        }
        uint4 x4 = *(const uint4*)(g_concat_h + (size_t)xb * H + xq * 8);
        *(uint4*)&Xt[xb * HPITCH + xq * 8] = x4;
    }
    __syncthreads();

    for (int t = 0; t < NT; t++) {
        int cur = t & 1;
        __half* Wc = Wt + cur * TVL * HPITCH;
        __half* Xc = Xt + cur * B * HPITCH;
        float4 wpre[4];
        uint4 xpre;
        if (t + 1 < NT) {
            int kc = (t + 1) * KCL;
#pragma unroll
            for (int r = 0; r < 4; r++) {
                int f = tid + r * 256;
                int v = f >> 3, kq = f & 7;
                wpre[r] = *(const float4*)(W + (size_t)(v0 + v) * H + kc + kq * 4);
            }
            xpre = *(const uint4*)(g_concat_h + (size_t)xb * H + kc + xq * 8);
        }

#pragma unroll
        for (int ks = 0; ks < 2; ks++) {
            int kf = ks * 16 + 2 * tig;
            uint32_t a[2][4];
#pragma unroll
            for (int mf = 0; mf < 2; mf++) {
                int mm = warpM * 32 + mf * 16 + grp;
                a[mf][0] = *(const uint32_t*)&Wc[mm * HPITCH + kf];
                a[mf][1] = *(const uint32_t*)&Wc[(mm + 8) * HPITCH + kf];
                a[mf][2] = *(const uint32_t*)&Wc[mm * HPITCH + kf + 8];
                a[mf][3] = *(const uint32_t*)&Wc[(mm + 8) * HPITCH + kf + 8];
            }
#pragma unroll
            for (int nf = 0; nf < 4; nf++) {
                int n = warpN * 32 + nf * 8 + grp;
                uint32_t b0 = *(const uint32_t*)&Xc[n * HPITCH + kf];
                uint32_t b1 = *(const uint32_t*)&Xc[n * HPITCH + kf + 8];
                mma_f16(acc[0][nf], a[0], b0, b1);
                mma_f16(acc[1][nf], a[1], b0, b1);
            }
        }

        if (t + 1 < NT) {
            __half* Wn = Wt + (cur ^ 1) * TVL * HPITCH;
            __half* Xn = Xt + (cur ^ 1) * B * HPITCH;
#pragma unroll
            for (int r = 0; r < 4; r++) {
                int f = tid + r * 256;
                int v = f >> 3, kq = f & 7;
                uint32_t p0 = h2pack(wpre[r].x, wpre[r].y);
                uint32_t p1 = h2pack(wpre[r].z, wpre[r].w);
                *(uint2*)&Wn[v * HPITCH + kq * 4] = make_uint2(p0, p1);
            }
            *(uint4*)&Xn[xb * HPITCH + xq * 8] = xpre;
        }
        __syncthreads();
    }

#pragma unroll
    for (int mf = 0; mf < 2; mf++) {
        int vr = v0 + warpM * 32 + mf * 16 + grp;
        float b0 = bias[vr], b1 = bias[vr + 8];
#pragma unroll
        for (int nf = 0; nf < 4; nf++) {
            int bcol = warpN * 32 + nf * 8 + 2 * tig;
            obase[(size_t)bcol * VP + vr]           = acc[mf][nf][0] + b0;
            obase[(size_t)(bcol + 1) * VP + vr]     = acc[mf][nf][1] + b0;
            obase[(size_t)bcol * VP + vr + 8]       = acc[mf][nf][2] + b1;
            obase[(size_t)(bcol + 1) * VP + vr + 8] = acc[mf][nf][3] + b1;
        }
    }
}

// ---------------------------------------------------------------------------
// attn-weights output softmax
// ---------------------------------------------------------------------------
__global__ void softmax_out_kernel(float* __restrict__ attn_out) {
    int b = blockIdx.x, tid = threadIdx.x;
    __shared__ float sh[8];
    __shared__ float sval;
    float m = -1e30f;
    for (int l = tid; l < L; l += 256) m = fmaxf(m, g_scores[b * L + l]);
#pragma unroll
    for (int o = 16; o; o >>= 1) m = fmaxf(m, __shfl_xor_sync(0xffffffffu, m, o));
    if ((tid & 31) == 0) sh[tid >> 5] = m;
    __syncthreads();
    if (tid == 0) {
        float mm = sh[0];
        for (int j = 1; j < 8; j++) mm = fmaxf(mm, sh[j]);
        sval = mm;
    }
    __syncthreads();
    m = sval;
    float s = 0.f;
    for (int l = tid; l < L; l += 256) s += expf(g_scores[b * L + l] - m);
    s = warp_sum(s);
    __syncthreads();
    if ((tid & 31) == 0) sh[tid >> 5] = s;
    __syncthreads();
    if (tid == 0) {
        float ss = 0.f;
        for (int j = 0; j < 8; j++) ss += sh[j];
        sval = ss;
    }
    __syncthreads();
    float inv = 1.f / sval;
    for (int l = tid; l < L; l += 256)
        attn_out[b * L + l] = expf(g_scores[b * L + l] - m) * inv;
}

// ---------------------------------------------------------------------------
extern "C" void kernel_launch(void* const* d_in, const int* in_sizes, int n_in,
                              void* d_out, int out_size) {
    const int*   seq         = (const int*)d_in[0];
    const float* last_hidden = (const float*)d_in[1];
    const float* enc         = (const float*)d_in[2];
    const float* emb         = (const float*)d_in[3];
    const float* w_ih        = (const float*)d_in[4];
    const float* w_hh        = (const float*)d_in[5];
    const float* b_ih        = (const float*)d_in[6];
    const float* b_hh        = (const float*)d_in[7];
    const float* concat_w    = (const float*)d_in[8];
    const float* concat_b    = (const float*)d_in[9];
    const float* owp         = (const float*)d_in[10];
    const float* obp         = (const float*)d_in[11];
    const float* owc         = (const float*)d_in[12];
    const float* obc         = (const float*)d_in[13];

    float* out        = (float*)d_out;
    float* out_hidden = out + (size_t)B * (VP + VC);
    float* out_attn   = out_hidden + (size_t)B * H;

    cudaFuncSetAttribute(gemm_part,  cudaFuncAttributeMaxDynamicSharedMemorySize, SM_G16);
    cudaFuncSetAttribute(logits_f16, cudaFuncAttributeMaxDynamicSharedMemorySize, SM_LOGF);

    float* gatep; cudaGetSymbolAddress((void**)&gatep, g_gatep);
    float* xh;    cudaGetSymbolAddress((void**)&xh, g_xh);
    float* hc;    cudaGetSymbolAddress((void**)&hc, g_hc);
    float* cpart; cudaGetSymbolAddress((void**)&cpart, g_cpart);

    pack_xh_kernel<<<B, 256>>>(seq, last_hidden, emb);
    gemm_part<<<dim3(48, GRU_SPLITS), 256, SM_G16>>>(
        w_ih, w_hh, xh, xh + (size_t)B * H, gatep,
        H, H / GRU_SPLITS, 24, GRU_ROWS);
    gru_gate_kernel<<<H / 4, 256>>>(last_hidden, b_ih, b_hh, out_hidden);
    flash2_kernel<<<dim3(B, CS), 256>>>(enc);          // 4th: profiled
    ctx_combine2_kernel<<<B, 256>>>();
    gemm_part<<<dim3(8, CAT_SPLITS), 256, SM_G16>>>(
        concat_w, nullptr, hc, nullptr, cpart,
        2 * H, 2 * H / CAT_SPLITS, 0, CAT_ROWS);
    cat_reduce_kernel<<<H / 4, 256>>>(concat_b);
    logits_f16<<<(VP + VC) / TVL, 256, SM_LOGF>>>(owp, obp, owc, obc, out);
    softmax_out_kernel<<<B, 256>>>(out_attn);
}